// round 10
// baseline (speedup 1.0000x reference)
#include <cuda_runtime.h>
#include <cuda_bf16.h>
#include <cstdint>

// Inputs (metadata order):
//   d_in[0] = x      float32 [262144]  (1 MB, random-gathered, L2-resident)
//   d_in[1] = A_vals float32 [NNZ]     (streamed once)
//   d_in[2] = A_rows int32   [NNZ]     (streamed once)
//   d_in[3] = A_cols int32   [NNZ]     (streamed once)
// Output: float32 [262144]
//
// Unsorted-COO SpMV at the co-saturated LSU/L1tex + LTS floor. R10: single
// fused launch — zero-init performed by the first 256 CTAs (guaranteed wave-1
// resident, CLC places bids contiguously), gated by a release/acquire counter
// before any scatter atomics. Counters self-reset via a finish counter so
// every graph replay is identical (no static-guard semantics).

#define ZCTAS      256        // zeroing CTAs; must be << wave-1 size (~1000)
#define THREADS    256

__device__ unsigned g_zero_done = 0;   // CTAs that finished zeroing
__device__ unsigned g_fin       = 0;   // CTAs that finished everything

__global__ void __launch_bounds__(THREADS) coo_spmv_fused_kernel(
    const float*  __restrict__ x,
    const float4* __restrict__ vals4,
    const int4*   __restrict__ rows4,
    const int4*   __restrict__ cols4,
    float*        __restrict__ out,
    int nnz4, int out4, int total_ctas)
{
    const int bid = blockIdx.x;
    const int tid = threadIdx.x;

    // ---- Phase 1: zero-init by the first ZCTAS CTAs (wave-1 guaranteed) ----
    if (bid < ZCTAS) {
        // out4 = out_size/4 float4 elements; each zero-CTA covers out4/ZCTAS.
        int per = out4 / ZCTAS;                  // 256 for this shape
        int base = bid * per;
        for (int j = tid; j < per; j += THREADS)
            ((float4*)out)[base + j] = make_float4(0.f, 0.f, 0.f, 0.f);
        // Remainder (out4 % ZCTAS) handled by CTA 0.
        if (bid == 0) {
            for (int j = ZCTAS * per + tid; j < out4; j += THREADS)
                ((float4*)out)[j] = make_float4(0.f, 0.f, 0.f, 0.f);
        }
        __threadfence();
        __syncthreads();
        if (tid == 0) atomicAdd(&g_zero_done, 1u);
    }

    // ---- Gate: no atomics until all of out is zeroed ----
    if (tid == 0) {
        unsigned v;
        do {
            asm volatile("ld.global.acquire.gpu.u32 %0, [%1];"
                         : "=r"(v) : "l"(&g_zero_done));
            if (v >= ZCTAS) break;
            __nanosleep(64);
        } while (true);
    }
    __syncthreads();

    // ---- Phase 2: COO SpMV (best-measured shape: 4 nnz/thread) ----
    int i = bid * THREADS + tid;
    if (i < nnz4) {
        float4 v = __ldg(&vals4[i]);
        int4   r = __ldg(&rows4[i]);
        int4   c = __ldg(&cols4[i]);

        float x0 = __ldg(&x[c.x]);
        float x1 = __ldg(&x[c.y]);
        float x2 = __ldg(&x[c.z]);
        float x3 = __ldg(&x[c.w]);

        atomicAdd(&out[r.x], v.x * x0);
        atomicAdd(&out[r.y], v.y * x1);
        atomicAdd(&out[r.z], v.z * x2);
        atomicAdd(&out[r.w], v.w * x3);
    }

    // ---- Epilogue: last CTA resets counters for the next graph replay ----
    __syncthreads();
    if (tid == 0) {
        __threadfence();
        unsigned d = atomicAdd(&g_fin, 1u);
        if (d == (unsigned)total_ctas - 1u) {
            g_zero_done = 0;
            g_fin = 0;
            __threadfence();
        }
    }
}

// Scalar tail (nnz % 4 != 0) — separate launch, unused for this shape.
__global__ void coo_spmv_tail_kernel(
    const float* __restrict__ x,
    const float* __restrict__ vals,
    const int*   __restrict__ rows,
    const int*   __restrict__ cols,
    float*       __restrict__ out,
    int start, int nnz)
{
    int i = start + blockIdx.x * blockDim.x + threadIdx.x;
    if (i < nnz) {
        atomicAdd(&out[rows[i]], vals[i] * __ldg(&x[cols[i]]));
    }
}

extern "C" void kernel_launch(void* const* d_in, const int* in_sizes, int n_in,
                              void* d_out, int out_size) {
    const float* x    = (const float*)d_in[0];
    const float* vals = (const float*)d_in[1];
    const int*   rows = (const int*)d_in[2];
    const int*   cols = (const int*)d_in[3];
    float* out = (float*)d_out;

    const int nnz  = in_sizes[1];
    const int nnz4 = nnz / 4;
    const int out4 = out_size / 4;       // out_size divisible by 4 here

    int blocks = (nnz4 + THREADS - 1) / THREADS;  // 8192 for this shape
    if (blocks < ZCTAS) blocks = ZCTAS;           // ensure all zero-CTAs exist

    coo_spmv_fused_kernel<<<blocks, THREADS>>>(
        x, (const float4*)vals, (const int4*)rows, (const int4*)cols,
        out, nnz4, out4, blocks);

    // Tail (nnz % 4): empty for this shape -> no node enters the graph.
    int tail_start = nnz4 * 4;
    int tail = nnz - tail_start;
    if (tail > 0) {
        coo_spmv_tail_kernel<<<(tail + 255) / 256, 256>>>(
            x, vals, rows, cols, out, tail_start, nnz);
    }
}

// round 11
// speedup vs baseline: 1.1793x; 1.1793x over previous
#include <cuda_runtime.h>
#include <cuda_bf16.h>
#include <cstdint>

// Inputs (metadata order):
//   d_in[0] = x      float32 [262144]  (1 MB, random-gathered, L2-resident)
//   d_in[1] = A_vals float32 [NNZ]     (streamed once)
//   d_in[2] = A_rows int32   [NNZ]     (streamed once)
//   d_in[3] = A_cols int32   [NNZ]     (streamed once)
// Output: float32 [262144]
//
// FINAL: unsorted-COO SpMV at the co-saturated L1tex/LTS floor (~66us kernel):
// 8.39M divergent 32B-sector gathers + 8.39M spread RED lanes + 100MB stream.
// Falsified across R2-R10: L1 cache-policy hints (x3 neutral), DSMEM cluster
// gather (3x worse), TMA-staged streams (neutral), smem x-slice (occupancy
// collapse), fused zero+gate single kernel (poll serialization, 25% worse).
// Best-measured configuration = R1: zero-kernel init + 4 nnz/thread,
// 256-thr blocks, 8192 CTAs, batched LDG.128 streams, RED.E.ADD.F32 scatter.

__global__ void zero_out_kernel(float4* __restrict__ out, int n4) {
    int i = blockIdx.x * blockDim.x + threadIdx.x;
    if (i < n4) out[i] = make_float4(0.f, 0.f, 0.f, 0.f);
}

__global__ void __launch_bounds__(256) coo_spmv_kernel(
    const float*  __restrict__ x,
    const float4* __restrict__ vals4,
    const int4*   __restrict__ rows4,
    const int4*   __restrict__ cols4,
    float*        __restrict__ out,
    int nnz4)
{
    int i = blockIdx.x * blockDim.x + threadIdx.x;
    if (i >= nnz4) return;

    // Three independent 16B streaming loads -> MLP 3 per thread.
    float4 v = __ldg(&vals4[i]);
    int4   r = __ldg(&rows4[i]);
    int4   c = __ldg(&cols4[i]);

    // Random gathers from L2-resident x (1 MB).
    float x0 = __ldg(&x[c.x]);
    float x1 = __ldg(&x[c.y]);
    float x2 = __ldg(&x[c.z]);
    float x3 = __ldg(&x[c.w]);

    // Scatter-add: return value unused -> RED.E.ADD.F32 at L2.
    atomicAdd(&out[r.x], v.x * x0);
    atomicAdd(&out[r.y], v.y * x1);
    atomicAdd(&out[r.z], v.z * x2);
    atomicAdd(&out[r.w], v.w * x3);
}

// Tail handler for nnz not divisible by 4 (host-guarded out for this shape).
__global__ void coo_spmv_tail_kernel(
    const float* __restrict__ x,
    const float* __restrict__ vals,
    const int*   __restrict__ rows,
    const int*   __restrict__ cols,
    float*       __restrict__ out,
    int start, int nnz)
{
    int i = start + blockIdx.x * blockDim.x + threadIdx.x;
    if (i < nnz) {
        atomicAdd(&out[rows[i]], vals[i] * __ldg(&x[cols[i]]));
    }
}

extern "C" void kernel_launch(void* const* d_in, const int* in_sizes, int n_in,
                              void* d_out, int out_size) {
    const float* x    = (const float*)d_in[0];
    const float* vals = (const float*)d_in[1];
    const int*   rows = (const int*)d_in[2];
    const int*   cols = (const int*)d_in[3];
    float* out = (float*)d_out;

    const int nnz = in_sizes[1];

    // Zero-init output (harness poisons it to 0xAA).
    {
        int n4 = out_size / 4;               // out_size divisible by 4 here
        zero_out_kernel<<<(n4 + 255) / 256, 256>>>((float4*)out, n4);
    }

    // Main vectorized COO pass: 4 nnz per thread (best-measured shape).
    int nnz4 = nnz / 4;
    if (nnz4 > 0) {
        int threads = 256;
        int blocks = (nnz4 + threads - 1) / threads;
        coo_spmv_kernel<<<blocks, threads>>>(
            x, (const float4*)vals, (const int4*)rows, (const int4*)cols, out, nnz4);
    }

    // Tail (nnz % 4): empty for this shape -> no node enters the graph.
    int tail_start = nnz4 * 4;
    int tail = nnz - tail_start;
    if (tail > 0) {
        coo_spmv_tail_kernel<<<(tail + 255) / 256, 256>>>(
            x, vals, rows, cols, out, tail_start, nnz);
    }
}

// round 12
// speedup vs baseline: 1.1863x; 1.0060x over previous
#include <cuda_runtime.h>
#include <cuda_bf16.h>
#include <cstdint>

// Inputs (metadata order):
//   d_in[0] = x      float32 [262144]  (1 MB, random-gathered, L2-resident)
//   d_in[1] = A_vals float32 [NNZ]     (streamed once)
//   d_in[2] = A_rows int32   [NNZ]     (streamed once)
//   d_in[3] = A_cols int32   [NNZ]     (streamed once)
// Output: float32 [262144]
//
// Unsorted-COO SpMV at the co-saturated L1tex/LTS floor (~66us kernel).
// R12 probe: 512-thread blocks (4096 CTAs) — the one untested geometry knob.
// Everything else identical to the best-measured R1 configuration.

#define THREADS 512

__global__ void zero_out_kernel(float4* __restrict__ out, int n4) {
    int i = blockIdx.x * blockDim.x + threadIdx.x;
    if (i < n4) out[i] = make_float4(0.f, 0.f, 0.f, 0.f);
}

__global__ void __launch_bounds__(THREADS) coo_spmv_kernel(
    const float*  __restrict__ x,
    const float4* __restrict__ vals4,
    const int4*   __restrict__ rows4,
    const int4*   __restrict__ cols4,
    float*        __restrict__ out,
    int nnz4)
{
    int i = blockIdx.x * blockDim.x + threadIdx.x;
    if (i >= nnz4) return;

    // Three independent 16B streaming loads -> MLP 3 per thread.
    float4 v = __ldg(&vals4[i]);
    int4   r = __ldg(&rows4[i]);
    int4   c = __ldg(&cols4[i]);

    // Random gathers from L2-resident x (1 MB).
    float x0 = __ldg(&x[c.x]);
    float x1 = __ldg(&x[c.y]);
    float x2 = __ldg(&x[c.z]);
    float x3 = __ldg(&x[c.w]);

    // Scatter-add: return value unused -> RED.E.ADD.F32 at L2.
    atomicAdd(&out[r.x], v.x * x0);
    atomicAdd(&out[r.y], v.y * x1);
    atomicAdd(&out[r.z], v.z * x2);
    atomicAdd(&out[r.w], v.w * x3);
}

// Tail handler for nnz not divisible by 4 (host-guarded out for this shape).
__global__ void coo_spmv_tail_kernel(
    const float* __restrict__ x,
    const float* __restrict__ vals,
    const int*   __restrict__ rows,
    const int*   __restrict__ cols,
    float*       __restrict__ out,
    int start, int nnz)
{
    int i = start + blockIdx.x * blockDim.x + threadIdx.x;
    if (i < nnz) {
        atomicAdd(&out[rows[i]], vals[i] * __ldg(&x[cols[i]]));
    }
}

extern "C" void kernel_launch(void* const* d_in, const int* in_sizes, int n_in,
                              void* d_out, int out_size) {
    const float* x    = (const float*)d_in[0];
    const float* vals = (const float*)d_in[1];
    const int*   rows = (const int*)d_in[2];
    const int*   cols = (const int*)d_in[3];
    float* out = (float*)d_out;

    const int nnz = in_sizes[1];

    // Zero-init output (harness poisons it to 0xAA).
    {
        int n4 = out_size / 4;               // out_size divisible by 4 here
        zero_out_kernel<<<(n4 + 255) / 256, 256>>>((float4*)out, n4);
    }

    // Main vectorized COO pass: 4 nnz per thread, 512-thread blocks.
    int nnz4 = nnz / 4;
    if (nnz4 > 0) {
        int blocks = (nnz4 + THREADS - 1) / THREADS;   // 4096 for this shape
        coo_spmv_kernel<<<blocks, THREADS>>>(
            x, (const float4*)vals, (const int4*)rows, (const int4*)cols, out, nnz4);
    }

    // Tail (nnz % 4): empty for this shape -> no node enters the graph.
    int tail_start = nnz4 * 4;
    int tail = nnz - tail_start;
    if (tail > 0) {
        coo_spmv_tail_kernel<<<(tail + 255) / 256, 256>>>(
            x, vals, rows, cols, out, tail_start, nnz);
    }
}